// round 3
// baseline (speedup 1.0000x reference)
#include <cuda_runtime.h>
#include <cuda_bf16.h>
#include <cstdint>

#define N_NODES 50000
#define E_EDGES 400000
#define E_TOT   450000   // edges + self loops
#define G_GRAPHS 256
#define HC 200           // H*C
#define C_CH 100
#define F_IN 336
#define SLOPE 0.2f

// ---------------- scratch (device globals: no allocation allowed) -------------
__device__ float g_x[N_NODES * HC];       // layer output (post-relu)
__device__ float g_h[N_NODES * HC];       // per-layer linear output
__device__ float g_es[N_NODES * 2];
__device__ float g_ed[N_NODES * 2];
__device__ float g_alpha[E_TOT * 2];
__device__ int   g_cnt[N_NODES];
__device__ int   g_rowptr[N_NODES + 1];
__device__ int   g_wr[N_NODES];
__device__ int   g_srcidx[E_TOT];
__device__ float g_pool[G_GRAPHS * HC];
__device__ int   g_pcnt[G_GRAPHS];
__device__ float g_t1[G_GRAPHS * 100];
__device__ float g_t2[G_GRAPHS * 100];

// ---------------- CSR build ---------------------------------------------------
__global__ void k_init_cnt() {
    int i = blockIdx.x * blockDim.x + threadIdx.x;
    if (i < N_NODES) g_cnt[i] = 1;   // self-loop
    if (i < G_GRAPHS) { g_pcnt[i] = 0; }
    if (i < G_GRAPHS * HC) g_pool[i] = 0.f;
}

__global__ void k_count(const int* __restrict__ ei) {
    int e = blockIdx.x * blockDim.x + threadIdx.x;
    if (e < E_EDGES) atomicAdd(&g_cnt[ei[E_EDGES + e]], 1);
}

__global__ void k_pcnt(const int* __restrict__ batch) {
    int i = blockIdx.x * blockDim.x + threadIdx.x;
    if (i < N_NODES) atomicAdd(&g_pcnt[batch[i]], 1);
}

__global__ void k_scan() {   // single block, 1024 threads
    const int n = N_NODES;
    int t = threadIdx.x;
    const int CHUNK = (n + 1023) / 1024;
    int start = t * CHUNK;
    int end = min(start + CHUNK, n);
    int sum = 0;
    for (int i = start; i < end; i++) sum += g_cnt[i];
    __shared__ int sh[1024];
    sh[t] = sum;
    __syncthreads();
    for (int off = 1; off < 1024; off <<= 1) {
        int v = (t >= off) ? sh[t - off] : 0;
        __syncthreads();
        sh[t] += v;
        __syncthreads();
    }
    int run = sh[t] - sum;   // exclusive
    for (int i = start; i < end; i++) {
        g_rowptr[i] = run;
        g_wr[i] = run;
        run += g_cnt[i];
    }
    if (t == 1023) g_rowptr[n] = sh[1023];
}

__global__ void k_scatter(const int* __restrict__ ei) {
    int e = blockIdx.x * blockDim.x + threadIdx.x;
    if (e >= E_TOT) return;
    int s, d;
    if (e < E_EDGES) { s = ei[e]; d = ei[E_EDGES + e]; }
    else             { s = d = e - E_EDGES; }
    int pos = atomicAdd(&g_wr[d], 1);
    g_srcidx[pos] = s;
}

__global__ void k_zero_sc() {
    int i = blockIdx.x * blockDim.x + threadIdx.x;
    if (i < N_NODES * 2) { g_es[i] = 0.f; g_ed[i] = 0.f; }
}

// ---------------- tf32x3 tensor-core GEMM + fused attention scores ------------
__device__ __forceinline__ void split_tf32(float v, float& hi, float& lo) {
    uint32_t u;
    asm("cvt.rna.tf32.f32 %0, %1;" : "=r"(u) : "f"(v));
    hi = __uint_as_float(u);
    float r = v - hi;
    asm("cvt.rna.tf32.f32 %0, %1;" : "=r"(u) : "f"(r));
    lo = __uint_as_float(u);
}

__device__ __forceinline__ void mma_tf32(float* c, const float* a, const float* b) {
    asm volatile(
        "mma.sync.aligned.m16n8k8.row.col.f32.tf32.tf32.f32 "
        "{%0,%1,%2,%3},{%4,%5,%6,%7},{%8,%9},{%0,%1,%2,%3};"
        : "+f"(c[0]), "+f"(c[1]), "+f"(c[2]), "+f"(c[3])
        : "r"(__float_as_uint(a[0])), "r"(__float_as_uint(a[1])),
          "r"(__float_as_uint(a[2])), "r"(__float_as_uint(a[3])),
          "r"(__float_as_uint(b[0])), "r"(__float_as_uint(b[1])));
}

// BM=128, BN=64, BK=16, 256 threads (8 warps as 4 row x 2 col, 32x32 warp tile)
__global__ void __launch_bounds__(256, 2)
k_gemm_tf32(const float* __restrict__ A, const float* __restrict__ B,
            float* __restrict__ C, int M, int K, int Nn,
            const float* __restrict__ asrc, const float* __restrict__ adst)
{
    const int BM = 128, BN = 64, BK = 16;
    __shared__ float As_hi[BM][BK + 4], As_lo[BM][BK + 4];
    __shared__ float Bs_hi[BK][BN + 8], Bs_lo[BK][BN + 8];
    __shared__ float sh_as[HC], sh_ad[HC];

    int tid = threadIdx.x;
    int rowBase = blockIdx.y * BM;
    int colBase = blockIdx.x * BN;
    int warpId = tid >> 5, lane = tid & 31;
    int wm = (warpId & 3) * 32;
    int wn = (warpId >> 2) * 32;
    int gr = lane >> 2;      // 0..7
    int cq = lane & 3;       // 0..3

    if (tid < HC) { sh_as[tid] = asrc[tid]; sh_ad[tid] = adst[tid]; }

    // how many n-frags of this warp carry valid columns
    int valid_n = Nn - colBase - wn;                // may be <=0
    int nt_lim = valid_n <= 0 ? 0 : (valid_n >= 32 ? 4 : ((valid_n + 7) >> 3));

    float acc[2][4][4];
#pragma unroll
    for (int i = 0; i < 2; i++)
#pragma unroll
        for (int j = 0; j < 4; j++)
#pragma unroll
            for (int k = 0; k < 4; k++) acc[i][j][k] = 0.f;

    int arow = tid >> 2;             // 0..63
    int acol = (tid & 3) * 4;        // 0,4,8,12
    int brow = tid >> 4;             // 0..15
    int bcol = (tid & 15) * 4;       // 0..60

    for (int k0 = 0; k0 < K; k0 += BK) {
        // stage A (128x16), pre-split
#pragma unroll
        for (int i = 0; i < 2; i++) {
            int m = arow + i * 64;
            int gm = rowBase + m;
            float4 v = make_float4(0.f, 0.f, 0.f, 0.f);
            int kk = k0 + acol;
            if (gm < M) {
                if (kk + 4 <= K) v = *(const float4*)(A + (long)gm * K + kk);
                else {
                    float* pv = &v.x;
                    for (int j = 0; j < 4; j++) if (kk + j < K) pv[j] = A[(long)gm * K + kk + j];
                }
            }
            float hi, lo;
            split_tf32(v.x, hi, lo); As_hi[m][acol]     = hi; As_lo[m][acol]     = lo;
            split_tf32(v.y, hi, lo); As_hi[m][acol + 1] = hi; As_lo[m][acol + 1] = lo;
            split_tf32(v.z, hi, lo); As_hi[m][acol + 2] = hi; As_lo[m][acol + 2] = lo;
            split_tf32(v.w, hi, lo); As_hi[m][acol + 3] = hi; As_lo[m][acol + 3] = lo;
        }
        // stage B (16x64), pre-split
        {
            int gk = k0 + brow;
            float4 v = make_float4(0.f, 0.f, 0.f, 0.f);
            if (gk < K) {
                int gn = colBase + bcol;
                if (gn + 4 <= Nn) v = *(const float4*)(B + (long)gk * Nn + gn);
                else {
                    float* pv = &v.x;
                    for (int j = 0; j < 4; j++) if (gn + j < Nn) pv[j] = B[(long)gk * Nn + gn + j];
                }
            }
            float hi, lo;
            split_tf32(v.x, hi, lo); Bs_hi[brow][bcol]     = hi; Bs_lo[brow][bcol]     = lo;
            split_tf32(v.y, hi, lo); Bs_hi[brow][bcol + 1] = hi; Bs_lo[brow][bcol + 1] = lo;
            split_tf32(v.z, hi, lo); Bs_hi[brow][bcol + 2] = hi; Bs_lo[brow][bcol + 2] = lo;
            split_tf32(v.w, hi, lo); Bs_hi[brow][bcol + 3] = hi; Bs_lo[brow][bcol + 3] = lo;
        }
        __syncthreads();

        if (nt_lim > 0) {
#pragma unroll
            for (int ks = 0; ks < 2; ks++) {
                int kb = ks * 8 + cq;
                float ah[2][4], al[2][4];
#pragma unroll
                for (int mt = 0; mt < 2; mt++) {
                    int m = wm + mt * 16 + gr;
                    ah[mt][0] = As_hi[m][kb];     al[mt][0] = As_lo[m][kb];
                    ah[mt][1] = As_hi[m + 8][kb]; al[mt][1] = As_lo[m + 8][kb];
                    ah[mt][2] = As_hi[m][kb + 4];     al[mt][2] = As_lo[m][kb + 4];
                    ah[mt][3] = As_hi[m + 8][kb + 4]; al[mt][3] = As_lo[m + 8][kb + 4];
                }
#pragma unroll
                for (int nt = 0; nt < 4; nt++) {
                    if (nt >= nt_lim) break;
                    int n = wn + nt * 8 + gr;
                    float bh[2], bl[2];
                    bh[0] = Bs_hi[kb][n];     bl[0] = Bs_lo[kb][n];
                    bh[1] = Bs_hi[kb + 4][n]; bl[1] = Bs_lo[kb + 4][n];
#pragma unroll
                    for (int mt = 0; mt < 2; mt++) {
                        float* c = acc[mt][nt];
                        mma_tf32(c, al[mt], bh);
                        mma_tf32(c, ah[mt], bl);
                        mma_tf32(c, ah[mt], bh);
                    }
                }
            }
        }
        __syncthreads();
    }

    // ---- epilogue: store C + fused es/ed partials ----
    float pes[2][2][2] = {}, ped[2][2][2] = {};   // [mt][half][head]

#pragma unroll
    for (int mt = 0; mt < 2; mt++) {
#pragma unroll
        for (int nt = 0; nt < 4; nt++) {
            int row = rowBase + wm + mt * 16 + gr;
            int col = colBase + wn + nt * 8 + cq * 2;
            float* c = acc[mt][nt];
            if (col + 1 < Nn) {
                if (row < M)     *(float2*)(C + (long)row * Nn + col)       = make_float2(c[0], c[1]);
                if (row + 8 < M) *(float2*)(C + (long)(row + 8) * Nn + col) = make_float2(c[2], c[3]);
            } else if (col < Nn) {
                if (row < M)     C[(long)row * Nn + col]       = c[0];
                if (row + 8 < M) C[(long)(row + 8) * Nn + col] = c[2];
            }
#pragma unroll
            for (int half = 0; half < 2; half++) {
#pragma unroll
                for (int j = 0; j < 2; j++) {
                    int cc = col + j;
                    if (cc < Nn) {
                        float v = c[half * 2 + j];
                        int h = (cc >= C_CH);
                        pes[mt][half][h] += v * sh_as[cc];
                        ped[mt][half][h] += v * sh_ad[cc];
                    }
                }
            }
        }
    }
    // reduce over cq (lanes xor 1, 2)
#pragma unroll
    for (int off = 1; off <= 2; off <<= 1) {
#pragma unroll
        for (int mt = 0; mt < 2; mt++)
#pragma unroll
            for (int half = 0; half < 2; half++)
#pragma unroll
                for (int h = 0; h < 2; h++) {
                    pes[mt][half][h] += __shfl_xor_sync(0xffffffffu, pes[mt][half][h], off);
                    ped[mt][half][h] += __shfl_xor_sync(0xffffffffu, ped[mt][half][h], off);
                }
    }
    if (cq == 0) {
#pragma unroll
        for (int mt = 0; mt < 2; mt++)
#pragma unroll
            for (int half = 0; half < 2; half++) {
                int row = rowBase + wm + mt * 16 + gr + half * 8;
                if (row < M) {
#pragma unroll
                    for (int h = 0; h < 2; h++) {
                        if (pes[mt][half][h] != 0.f) atomicAdd(&g_es[row * 2 + h], pes[mt][half][h]);
                        if (ped[mt][half][h] != 0.f) atomicAdd(&g_ed[row * 2 + h], ped[mt][half][h]);
                    }
                }
            }
    }
}

// ---------------- softmax + aggregate + bias + relu (warp per dst) ------------
__device__ __forceinline__ float lrelu(float e) { return e > 0.f ? e : SLOPE * e; }

__global__ void k_aggregate(const float* __restrict__ bc, int do_pool,
                            const int* __restrict__ batch) {
    int gwarp = (blockIdx.x * blockDim.x + threadIdx.x) >> 5;
    int lane  = threadIdx.x & 31;
    if (gwarp >= N_NODES) return;
    int dst = gwarp;
    int beg = g_rowptr[dst], end = g_rowptr[dst + 1];
    float ed0 = g_ed[dst * 2], ed1 = g_ed[dst * 2 + 1];

    float m0 = -1e30f, m1 = -1e30f;
    for (int i = beg + lane; i < end; i += 32) {
        int s = g_srcidx[i];
        m0 = fmaxf(m0, lrelu(g_es[s * 2]     + ed0));
        m1 = fmaxf(m1, lrelu(g_es[s * 2 + 1] + ed1));
    }
#pragma unroll
    for (int o = 16; o; o >>= 1) {
        m0 = fmaxf(m0, __shfl_xor_sync(0xffffffffu, m0, o));
        m1 = fmaxf(m1, __shfl_xor_sync(0xffffffffu, m1, o));
    }

    float s0 = 0.f, s1 = 0.f;
    for (int i = beg + lane; i < end; i += 32) {
        int s = g_srcidx[i];
        float p0 = __expf(lrelu(g_es[s * 2]     + ed0) - m0);
        float p1 = __expf(lrelu(g_es[s * 2 + 1] + ed1) - m1);
        g_alpha[i * 2]     = p0;
        g_alpha[i * 2 + 1] = p1;
        s0 += p0; s1 += p1;
    }
#pragma unroll
    for (int o = 16; o; o >>= 1) {
        s0 += __shfl_xor_sync(0xffffffffu, s0, o);
        s1 += __shfl_xor_sync(0xffffffffu, s1, o);
    }
    float inv0 = 1.f / (s0 + 1e-16f);
    float inv1 = 1.f / (s1 + 1e-16f);

    // channel blocks: i4 = lane (k=0) and 32+lane (k=1, lane<18); 50 float4 = 200 ch
    float4 a0v = make_float4(0.f, 0.f, 0.f, 0.f), a1v = a0v;
    int i4_0 = lane;            // always < 50
    int i4_1 = 32 + lane;       // valid if < 50
    bool has1 = (i4_1 < 50);

    for (int i = beg; i < end; i++) {
        int s = g_srcidx[i];
        float aa0 = g_alpha[i * 2]     * inv0;
        float aa1 = g_alpha[i * 2 + 1] * inv1;
        const float4* hr = (const float4*)(g_h + (long)s * HC);
        {
            float4 v = hr[i4_0];
            float a = (i4_0 < 25) ? aa0 : aa1;
            a0v.x += a * v.x; a0v.y += a * v.y; a0v.z += a * v.z; a0v.w += a * v.w;
        }
        if (has1) {
            float4 v = hr[i4_1];
            float a = (i4_1 < 25) ? aa0 : aa1;
            a1v.x += a * v.x; a1v.y += a * v.y; a1v.z += a * v.z; a1v.w += a * v.w;
        }
    }

    const float4* bc4 = (const float4*)bc;
    float4 b0 = bc4[i4_0];
    float4 o0 = make_float4(fmaxf(a0v.x + b0.x, 0.f), fmaxf(a0v.y + b0.y, 0.f),
                            fmaxf(a0v.z + b0.z, 0.f), fmaxf(a0v.w + b0.w, 0.f));
    float4 o1 = make_float4(0.f, 0.f, 0.f, 0.f);
    if (has1) {
        float4 b1 = bc4[i4_1];
        o1 = make_float4(fmaxf(a1v.x + b1.x, 0.f), fmaxf(a1v.y + b1.y, 0.f),
                         fmaxf(a1v.z + b1.z, 0.f), fmaxf(a1v.w + b1.w, 0.f));
    }

    if (!do_pool) {
        float4* xr = (float4*)(g_x + (long)dst * HC);
        xr[i4_0] = o0;
        if (has1) xr[i4_1] = o1;
    } else {
        int b = batch[dst];
        float* pp = g_pool + b * HC;
        int c0 = i4_0 * 4;
        atomicAdd(pp + c0, o0.x); atomicAdd(pp + c0 + 1, o0.y);
        atomicAdd(pp + c0 + 2, o0.z); atomicAdd(pp + c0 + 3, o0.w);
        if (has1) {
            int c1 = i4_1 * 4;
            atomicAdd(pp + c1, o1.x); atomicAdd(pp + c1 + 1, o1.y);
            atomicAdd(pp + c1 + 2, o1.z); atomicAdd(pp + c1 + 3, o1.w);
        }
    }
}

// ---------------- tiny MLP layer (one block per graph) ------------------------
__global__ void k_mlp(const float* __restrict__ A, const float* __restrict__ Wm,
                      const float* __restrict__ bm, float* __restrict__ out,
                      int K, int Nn, int do_relu, int do_div) {
    int g = blockIdx.x;
    __shared__ float arow[HC];
    float inv = 1.f;
    if (do_div) inv = 1.f / fmaxf((float)g_pcnt[g], 1.f);
    for (int i = threadIdx.x; i < K; i += blockDim.x) arow[i] = A[g * K + i] * inv;
    __syncthreads();
    for (int j = threadIdx.x; j < Nn; j += blockDim.x) {
        float acc = bm[j];
        for (int k = 0; k < K; k++) acc += arow[k] * Wm[k * Nn + j];
        if (do_relu) acc = fmaxf(acc, 0.f);
        out[g * Nn + j] = acc;
    }
}

// ---------------- launch ------------------------------------------------------
extern "C" void kernel_launch(void* const* d_in, const int* in_sizes, int n_in,
                              void* d_out, int out_size) {
    const float* x    = (const float*)d_in[0];
    const int*   ei   = (const int*)d_in[1];
    const int*   batch= (const int*)d_in[2];
    const float *W[5], *as_[5], *ad_[5], *bc_[5];
    for (int i = 0; i < 5; i++) {
        W[i]   = (const float*)d_in[3 + 4 * i];
        as_[i] = (const float*)d_in[4 + 4 * i];
        ad_[i] = (const float*)d_in[5 + 4 * i];
        bc_[i] = (const float*)d_in[6 + 4 * i];
    }
    const float* lw1 = (const float*)d_in[23];
    const float* lb1 = (const float*)d_in[24];
    const float* lw2 = (const float*)d_in[25];
    const float* lb2 = (const float*)d_in[26];
    const float* lw3 = (const float*)d_in[27];
    const float* lb3 = (const float*)d_in[28];

    float *px, *ph, *ppool, *pt1, *pt2;
    cudaGetSymbolAddress((void**)&px, g_x);
    cudaGetSymbolAddress((void**)&ph, g_h);
    cudaGetSymbolAddress((void**)&ppool, g_pool);
    cudaGetSymbolAddress((void**)&pt1, g_t1);
    cudaGetSymbolAddress((void**)&pt2, g_t2);

    // CSR (fixed topology, rebuilt each launch for determinism)
    k_init_cnt<<<(G_GRAPHS * HC + 255) / 256, 256>>>();
    k_count<<<(E_EDGES + 255) / 256, 256>>>(ei);
    k_pcnt<<<(N_NODES + 255) / 256, 256>>>(batch);
    k_scan<<<1, 1024>>>();
    k_scatter<<<(E_TOT + 255) / 256, 256>>>(ei);

    const float* xin = x;
    int K = F_IN;
    int warpGrid = (N_NODES * 32 + 255) / 256;
    for (int l = 0; l < 5; l++) {
        k_zero_sc<<<(N_NODES * 2 + 255) / 256, 256>>>();
        dim3 grid((HC + 63) / 64, (N_NODES + 127) / 128);
        k_gemm_tf32<<<grid, 256>>>(xin, W[l], ph, N_NODES, K, HC, as_[l], ad_[l]);
        k_aggregate<<<warpGrid, 256>>>(bc_[l], l == 4 ? 1 : 0, batch);
        xin = px;
        K = HC;
    }

    k_mlp<<<G_GRAPHS, 128>>>(ppool, lw1, lb1, pt1, 200, 100, 1, 1);
    k_mlp<<<G_GRAPHS, 128>>>(pt1, lw2, lb2, pt2, 100, 100, 1, 0);
    k_mlp<<<G_GRAPHS, 128>>>(pt2, lw3, lb3, (float*)d_out, 100, 29, 0, 0);
}

// round 4
// speedup vs baseline: 1.1945x; 1.1945x over previous
#include <cuda_runtime.h>
#include <cuda_bf16.h>
#include <cstdint>

#define N_NODES 50000
#define E_EDGES 400000
#define E_TOT   450000   // edges + self loops
#define G_GRAPHS 256
#define HC 200           // H*C
#define C_CH 100
#define F_IN 336
#define SLOPE 0.2f
#define NB_SCAN 49       // ceil(50000/1024)

// ---------------- scratch (device globals: no allocation allowed) -------------
__device__ float g_x[N_NODES * HC];       // layer output (post-relu)
__device__ float g_h[N_NODES * HC];       // per-layer linear output
__device__ float g_es[N_NODES * 2];
__device__ float g_ed[N_NODES * 2];
__device__ float g_alpha[E_TOT * 2];
__device__ int   g_cnt[N_NODES];
__device__ int   g_rowptr[N_NODES + 1];
__device__ int   g_wr[N_NODES];
__device__ int   g_srcidx[E_TOT];
__device__ int   g_bsum[NB_SCAN];
__device__ float g_pool[G_GRAPHS * HC];
__device__ int   g_pcnt[G_GRAPHS];
__device__ float g_t1[G_GRAPHS * 100];
__device__ float g_t2[G_GRAPHS * 100];

// ---------------- CSR build ---------------------------------------------------
__global__ void k_init_cnt() {
    int i = blockIdx.x * blockDim.x + threadIdx.x;
    if (i < N_NODES) g_cnt[i] = 1;   // self-loop
    if (i < G_GRAPHS) g_pcnt[i] = 0;
    if (i < G_GRAPHS * HC) g_pool[i] = 0.f;
}

__global__ void k_count(const int* __restrict__ ei) {
    int e = blockIdx.x * blockDim.x + threadIdx.x;
    if (e < E_EDGES) atomicAdd(&g_cnt[ei[E_EDGES + e]], 1);
}

__global__ void k_pcnt(const int* __restrict__ batch) {
    int i = blockIdx.x * blockDim.x + threadIdx.x;
    if (i < N_NODES) atomicAdd(&g_pcnt[batch[i]], 1);
}

// stage 1: per-block (1024 elems) sums, 256 threads/block, coalesced
__global__ void k_bsum() {
    __shared__ int sh[256];
    int b = blockIdx.x, t = threadIdx.x;
    int base = b * 1024;
    int s = 0;
#pragma unroll
    for (int j = 0; j < 4; j++) {
        int i = base + t + j * 256;
        if (i < N_NODES) s += g_cnt[i];
    }
    sh[t] = s; __syncthreads();
    for (int off = 128; off; off >>= 1) {
        if (t < off) sh[t] += sh[t + off];
        __syncthreads();
    }
    if (t == 0) g_bsum[b] = sh[0];
}

// stage 2: exclusive scan of NB_SCAN block sums (trivial size)
__global__ void k_bscan() {
    if (threadIdx.x == 0) {
        int run = 0;
        for (int b = 0; b < NB_SCAN; b++) { int v = g_bsum[b]; g_bsum[b] = run; run += v; }
    }
}

// stage 3: per-block prefix, write rowptr/wr
__global__ void k_rowptr() {
    __shared__ int sh[256];
    int b = blockIdx.x, t = threadIdx.x;
    int i0 = b * 1024 + t * 4;
    int c[4]; int local = 0;
#pragma unroll
    for (int j = 0; j < 4; j++) {
        int i = i0 + j;
        c[j] = (i < N_NODES) ? g_cnt[i] : 0;
        local += c[j];
    }
    sh[t] = local; __syncthreads();
    for (int off = 1; off < 256; off <<= 1) {
        int v = (t >= off) ? sh[t - off] : 0;
        __syncthreads();
        sh[t] += v;
        __syncthreads();
    }
    int run = g_bsum[b] + sh[t] - local;   // exclusive prefix
#pragma unroll
    for (int j = 0; j < 4; j++) {
        int i = i0 + j;
        if (i < N_NODES) { g_rowptr[i] = run; g_wr[i] = run; run += c[j]; }
    }
    if (b == 0 && t == 0) g_rowptr[N_NODES] = E_TOT;
}

__global__ void k_scatter(const int* __restrict__ ei) {
    int e = blockIdx.x * blockDim.x + threadIdx.x;
    if (e >= E_TOT) return;
    int s, d;
    if (e < E_EDGES) { s = ei[e]; d = ei[E_EDGES + e]; }
    else             { s = d = e - E_EDGES; }
    int pos = atomicAdd(&g_wr[d], 1);
    g_srcidx[pos] = s;
}

// ---------------- tf32x3 tensor-core GEMM (Round-2 proven config) -------------
__device__ __forceinline__ void split_tf32(float v, uint32_t& hi, uint32_t& lo) {
    asm("cvt.rna.tf32.f32 %0, %1;" : "=r"(hi) : "f"(v));
    float h = __uint_as_float(hi);
    float r = v - h;
    asm("cvt.rna.tf32.f32 %0, %1;" : "=r"(lo) : "f"(r));
}

__device__ __forceinline__ void mma_tf32(float* c,
                                         const uint32_t* a, const uint32_t* b) {
    asm volatile(
        "mma.sync.aligned.m16n8k8.row.col.f32.tf32.tf32.f32 "
        "{%0,%1,%2,%3},{%4,%5,%6,%7},{%8,%9},{%0,%1,%2,%3};"
        : "+f"(c[0]), "+f"(c[1]), "+f"(c[2]), "+f"(c[3])
        : "r"(a[0]), "r"(a[1]), "r"(a[2]), "r"(a[3]), "r"(b[0]), "r"(b[1]));
}

__global__ void __launch_bounds__(256)
k_gemm_tf32(const float* __restrict__ A, const float* __restrict__ B,
            float* __restrict__ C, int M, int K, int Nn)
{
    const int BM = 128, BN = 64, BK = 32;
    __shared__ float As[BM][36];
    __shared__ float Bs[BK][72];

    int tid = threadIdx.x;
    int rowBase = blockIdx.y * BM;
    int colBase = blockIdx.x * BN;
    int warpId = tid >> 5, lane = tid & 31;
    int wm = (warpId & 3) * 32;
    int wn = (warpId >> 2) * 32;
    int gr = lane >> 2;
    int cq = lane & 3;

    float acc[2][4][4];
#pragma unroll
    for (int i = 0; i < 2; i++)
#pragma unroll
        for (int j = 0; j < 4; j++)
#pragma unroll
            for (int k = 0; k < 4; k++) acc[i][j][k] = 0.f;

    int arow = tid >> 3;
    int acol = (tid & 7) * 4;
    int brow = tid >> 4;
    int bcol = (tid & 15) * 4;

    for (int k0 = 0; k0 < K; k0 += BK) {
#pragma unroll
        for (int i = 0; i < 4; i++) {
            int m = arow + i * 32;
            int gm = rowBase + m;
            float4 v = make_float4(0.f, 0.f, 0.f, 0.f);
            if (gm < M && (k0 + acol) < K)
                v = *(const float4*)(A + (long)gm * K + k0 + acol);
            *(float4*)&As[m][acol] = v;
        }
#pragma unroll
        for (int i = 0; i < 2; i++) {
            int kk = brow + i * 16;
            int gk = k0 + kk;
            float4 v = make_float4(0.f, 0.f, 0.f, 0.f);
            if (gk < K && (colBase + bcol) < Nn)
                v = *(const float4*)(B + (long)gk * Nn + colBase + bcol);
            *(float4*)&Bs[kk][bcol] = v;
        }
        __syncthreads();

#pragma unroll
        for (int ks = 0; ks < 4; ks++) {
            int kb = ks * 8 + cq;
            uint32_t ah[2][4], al[2][4];
#pragma unroll
            for (int mt = 0; mt < 2; mt++) {
                int m = wm + mt * 16 + gr;
                split_tf32(As[m][kb],         ah[mt][0], al[mt][0]);
                split_tf32(As[m + 8][kb],     ah[mt][1], al[mt][1]);
                split_tf32(As[m][kb + 4],     ah[mt][2], al[mt][2]);
                split_tf32(As[m + 8][kb + 4], ah[mt][3], al[mt][3]);
            }
            uint32_t bh[4][2], bl[4][2];
#pragma unroll
            for (int nt = 0; nt < 4; nt++) {
                int n = wn + nt * 8 + gr;
                split_tf32(Bs[kb][n],     bh[nt][0], bl[nt][0]);
                split_tf32(Bs[kb + 4][n], bh[nt][1], bl[nt][1]);
            }
#pragma unroll
            for (int mt = 0; mt < 2; mt++)
#pragma unroll
                for (int nt = 0; nt < 4; nt++) {
                    float* c = acc[mt][nt];
                    mma_tf32(c, al[mt], bh[nt]);
                    mma_tf32(c, ah[mt], bl[nt]);
                    mma_tf32(c, ah[mt], bh[nt]);
                }
        }
        __syncthreads();
    }

#pragma unroll
    for (int mt = 0; mt < 2; mt++) {
#pragma unroll
        for (int nt = 0; nt < 4; nt++) {
            int row = rowBase + wm + mt * 16 + gr;
            int col = colBase + wn + nt * 8 + cq * 2;
            float* c = acc[mt][nt];
            if (col < Nn) {
                if (row < M) {
                    float2 v = make_float2(c[0], c[1]);
                    *(float2*)(C + (long)row * Nn + col) = v;
                }
                if (row + 8 < M) {
                    float2 v = make_float2(c[2], c[3]);
                    *(float2*)(C + (long)(row + 8) * Nn + col) = v;
                }
            }
        }
    }
}

// ---------------- attention source/dest scores (warp per node) ----------------
__global__ void k_scores(const float* __restrict__ asrc, const float* __restrict__ adst) {
    int gwarp = (blockIdx.x * blockDim.x + threadIdx.x) >> 5;
    int lane  = threadIdx.x & 31;
    if (gwarp >= N_NODES) return;
    const float* hr = g_h + (long)gwarp * HC;
    float es0 = 0.f, es1 = 0.f, ed0 = 0.f, ed1 = 0.f;
    for (int c = lane; c < HC; c += 32) {
        float v = hr[c], a = asrc[c], d = adst[c];
        if (c < C_CH) { es0 += v * a; ed0 += v * d; }
        else          { es1 += v * a; ed1 += v * d; }
    }
#pragma unroll
    for (int o = 16; o; o >>= 1) {
        es0 += __shfl_xor_sync(0xffffffffu, es0, o);
        es1 += __shfl_xor_sync(0xffffffffu, es1, o);
        ed0 += __shfl_xor_sync(0xffffffffu, ed0, o);
        ed1 += __shfl_xor_sync(0xffffffffu, ed1, o);
    }
    if (lane == 0) {
        g_es[gwarp * 2]     = es0;
        g_es[gwarp * 2 + 1] = es1;
        g_ed[gwarp * 2]     = ed0;
        g_ed[gwarp * 2 + 1] = ed1;
    }
}

// ---------------- softmax + aggregate + bias + relu (warp per dst) ------------
__device__ __forceinline__ float lrelu(float e) { return e > 0.f ? e : SLOPE * e; }

__global__ void k_aggregate(const float* __restrict__ bc, int do_pool,
                            const int* __restrict__ batch) {
    int gwarp = (blockIdx.x * blockDim.x + threadIdx.x) >> 5;
    int lane  = threadIdx.x & 31;
    if (gwarp >= N_NODES) return;
    int dst = gwarp;
    int beg = g_rowptr[dst], end = g_rowptr[dst + 1];
    float ed0 = g_ed[dst * 2], ed1 = g_ed[dst * 2 + 1];

    float m0 = -1e30f, m1 = -1e30f;
    for (int i = beg + lane; i < end; i += 32) {
        int s = g_srcidx[i];
        m0 = fmaxf(m0, lrelu(g_es[s * 2]     + ed0));
        m1 = fmaxf(m1, lrelu(g_es[s * 2 + 1] + ed1));
    }
#pragma unroll
    for (int o = 16; o; o >>= 1) {
        m0 = fmaxf(m0, __shfl_xor_sync(0xffffffffu, m0, o));
        m1 = fmaxf(m1, __shfl_xor_sync(0xffffffffu, m1, o));
    }

    float s0 = 0.f, s1 = 0.f;
    for (int i = beg + lane; i < end; i += 32) {
        int s = g_srcidx[i];
        float p0 = __expf(lrelu(g_es[s * 2]     + ed0) - m0);
        float p1 = __expf(lrelu(g_es[s * 2 + 1] + ed1) - m1);
        g_alpha[i * 2]     = p0;
        g_alpha[i * 2 + 1] = p1;
        s0 += p0; s1 += p1;
    }
#pragma unroll
    for (int o = 16; o; o >>= 1) {
        s0 += __shfl_xor_sync(0xffffffffu, s0, o);
        s1 += __shfl_xor_sync(0xffffffffu, s1, o);
    }
    float inv0 = 1.f / (s0 + 1e-16f);
    float inv1 = 1.f / (s1 + 1e-16f);

    // float4 channel blocks: i4_0 = lane (<50 always), i4_1 = 32+lane (<50 if lane<18)
    float4 a0v = make_float4(0.f, 0.f, 0.f, 0.f), a1v = a0v;
    int i4_0 = lane;
    int i4_1 = 32 + lane;
    bool has1 = (i4_1 < 50);

    for (int i = beg; i < end; i++) {
        int s = g_srcidx[i];
        float aa0 = g_alpha[i * 2]     * inv0;
        float aa1 = g_alpha[i * 2 + 1] * inv1;
        const float4* hr = (const float4*)(g_h + (long)s * HC);
        {
            float4 v = hr[i4_0];
            float a = (i4_0 < 25) ? aa0 : aa1;
            a0v.x += a * v.x; a0v.y += a * v.y; a0v.z += a * v.z; a0v.w += a * v.w;
        }
        if (has1) {
            float4 v = hr[i4_1];
            float a = (i4_1 < 25) ? aa0 : aa1;
            a1v.x += a * v.x; a1v.y += a * v.y; a1v.z += a * v.z; a1v.w += a * v.w;
        }
    }

    const float4* bc4 = (const float4*)bc;
    float4 b0 = bc4[i4_0];
    float4 o0 = make_float4(fmaxf(a0v.x + b0.x, 0.f), fmaxf(a0v.y + b0.y, 0.f),
                            fmaxf(a0v.z + b0.z, 0.f), fmaxf(a0v.w + b0.w, 0.f));
    float4 o1 = make_float4(0.f, 0.f, 0.f, 0.f);
    if (has1) {
        float4 b1 = bc4[i4_1];
        o1 = make_float4(fmaxf(a1v.x + b1.x, 0.f), fmaxf(a1v.y + b1.y, 0.f),
                         fmaxf(a1v.z + b1.z, 0.f), fmaxf(a1v.w + b1.w, 0.f));
    }

    if (!do_pool) {
        float4* xr = (float4*)(g_x + (long)dst * HC);
        xr[i4_0] = o0;
        if (has1) xr[i4_1] = o1;
    } else {
        int b = batch[dst];
        float* pp = g_pool + b * HC;
        int c0 = i4_0 * 4;
        atomicAdd(pp + c0, o0.x); atomicAdd(pp + c0 + 1, o0.y);
        atomicAdd(pp + c0 + 2, o0.z); atomicAdd(pp + c0 + 3, o0.w);
        if (has1) {
            int c1 = i4_1 * 4;
            atomicAdd(pp + c1, o1.x); atomicAdd(pp + c1 + 1, o1.y);
            atomicAdd(pp + c1 + 2, o1.z); atomicAdd(pp + c1 + 3, o1.w);
        }
    }
}

// ---------------- tiny MLP layer (one block per graph) ------------------------
__global__ void k_mlp(const float* __restrict__ A, const float* __restrict__ Wm,
                      const float* __restrict__ bm, float* __restrict__ out,
                      int K, int Nn, int do_relu, int do_div) {
    int g = blockIdx.x;
    __shared__ float arow[HC];
    float inv = 1.f;
    if (do_div) inv = 1.f / fmaxf((float)g_pcnt[g], 1.f);
    for (int i = threadIdx.x; i < K; i += blockDim.x) arow[i] = A[g * K + i] * inv;
    __syncthreads();
    for (int j = threadIdx.x; j < Nn; j += blockDim.x) {
        float acc = bm[j];
        for (int k = 0; k < K; k++) acc += arow[k] * Wm[k * Nn + j];
        if (do_relu) acc = fmaxf(acc, 0.f);
        out[g * Nn + j] = acc;
    }
}

// ---------------- launch ------------------------------------------------------
extern "C" void kernel_launch(void* const* d_in, const int* in_sizes, int n_in,
                              void* d_out, int out_size) {
    const float* x    = (const float*)d_in[0];
    const int*   ei   = (const int*)d_in[1];
    const int*   batch= (const int*)d_in[2];
    const float *W[5], *as_[5], *ad_[5], *bc_[5];
    for (int i = 0; i < 5; i++) {
        W[i]   = (const float*)d_in[3 + 4 * i];
        as_[i] = (const float*)d_in[4 + 4 * i];
        ad_[i] = (const float*)d_in[5 + 4 * i];
        bc_[i] = (const float*)d_in[6 + 4 * i];
    }
    const float* lw1 = (const float*)d_in[23];
    const float* lb1 = (const float*)d_in[24];
    const float* lw2 = (const float*)d_in[25];
    const float* lb2 = (const float*)d_in[26];
    const float* lw3 = (const float*)d_in[27];
    const float* lb3 = (const float*)d_in[28];

    float *px, *ph, *ppool, *pt1, *pt2;
    cudaGetSymbolAddress((void**)&px, g_x);
    cudaGetSymbolAddress((void**)&ph, g_h);
    cudaGetSymbolAddress((void**)&ppool, g_pool);
    cudaGetSymbolAddress((void**)&pt1, g_t1);
    cudaGetSymbolAddress((void**)&pt2, g_t2);

    // CSR (fixed topology, rebuilt each launch for determinism)
    k_init_cnt<<<(G_GRAPHS * HC + 255) / 256, 256>>>();
    k_count<<<(E_EDGES + 255) / 256, 256>>>(ei);
    k_pcnt<<<(N_NODES + 255) / 256, 256>>>(batch);
    k_bsum<<<NB_SCAN, 256>>>();
    k_bscan<<<1, 32>>>();
    k_rowptr<<<NB_SCAN, 256>>>();
    k_scatter<<<(E_TOT + 255) / 256, 256>>>(ei);

    const float* xin = x;
    int K = F_IN;
    int warpGrid = (N_NODES * 32 + 255) / 256;
    for (int l = 0; l < 5; l++) {
        dim3 grid((HC + 63) / 64, (N_NODES + 127) / 128);
        k_gemm_tf32<<<grid, 256>>>(xin, W[l], ph, N_NODES, K, HC);
        k_scores<<<warpGrid, 256>>>(as_[l], ad_[l]);
        k_aggregate<<<warpGrid, 256>>>(bc_[l], l == 4 ? 1 : 0, batch);
        xin = px;
        K = HC;
    }

    k_mlp<<<G_GRAPHS, 128>>>(ppool, lw1, lb1, pt1, 200, 100, 1, 1);
    k_mlp<<<G_GRAPHS, 128>>>(pt1, lw2, lb2, pt2, 100, 100, 1, 0);
    k_mlp<<<G_GRAPHS, 128>>>(pt2, lw3, lb3, (float*)d_out, 100, 29, 0, 0);
}